// round 11
// baseline (speedup 1.0000x reference)
#include <cuda_runtime.h>
#include <math.h>

#define BB 8
#define AA 49104
#define MM 50
#define KK 80
#define TPB 256
#define NBLKX_SCR ((AA + TPB - 1) / TPB)     // 192
#define NBLKX_SWP 148
#define NBLKS_SWP (NBLKX_SWP * BB)           // 1184

// zero-initialized at module load; finalizer re-zeros after each consume,
// so every graph replay starts clean.
__device__ float g_cls_raw[BB];
__device__ float g_reg_raw[BB];
__device__ int   g_numpos[BB];
__device__ unsigned int g_done;
__device__ float g_wgt[BB * AA];   // per-anchor cls-loss weight (0/1), 1.5 MB

__device__ __forceinline__ float smooth_l1(float d) {
    const float BETA = 1.0f / 9.0f;
    float ad = fabsf(d);
    return (ad <= BETA) ? (4.5f * ad * ad) : (ad - 0.5f * BETA);
}

// focal bulk term for one float4 of probabilities: sum p^2 * log2(1-p)
__device__ __forceinline__ float focal4(float4 p4) {
    return p4.x * p4.x * __log2f(1.0f - p4.x)
         + p4.y * p4.y * __log2f(1.0f - p4.y)
         + p4.z * p4.z * __log2f(1.0f - p4.z)
         + p4.w * p4.w * __log2f(1.0f - p4.w);
}

// ============================================================================
// Kernel 1: assignment screen + positive-anchor corrections
// ============================================================================
__global__ __launch_bounds__(TPB, 6) void screen_kernel(
    const float* __restrict__ logits,
    const float* __restrict__ regp,
    const float* __restrict__ anchors,
    const float* __restrict__ boxes,
    const int*   __restrict__ cls)
{
    const int b = blockIdx.y;
    const int tid = threadIdx.x;
    const int a = blockIdx.x * TPB + tid;

    __shared__ float4 sbox[MM];
    __shared__ float4 saux[MM];   // (2/7)sb, (1/3)sb, sb, cls-bits
    __shared__ int    splist[TPB];
    __shared__ int    spcnt, snv;
    __shared__ float  wsum[8], wsum2[8];

    if (tid == 0) { spcnt = 0; snv = MM; }
    __syncthreads();
    if (tid < MM) {
        float4 bx = ((const float4*)boxes)[b * MM + tid];
        float sb = (bx.z - bx.x) * (bx.w - bx.y);
        sbox[tid] = bx;
        float4 au;
        au.x = sb * (2.0f / 7.0f);   // 0.4/(1+0.4) * sb
        au.y = sb * (1.0f / 3.0f);   // 0.5/(1+0.5) * sb
        au.z = sb;
        au.w = __int_as_float(cls[b * MM + tid]);
        saux[tid] = au;
        if (bx.x == -1.0f) atomicMin(&snv, tid);   // valid-first padding
    }
    __syncthreads();
    const int nv = snv;   // uniform -> no divergence

    float s = 0.0f, rsum = 0.0f;

    // ---- screen: iou >= t <=> inter >= t/(1+t)*(sa+sb), FFMA-fused ----
    if (a < AA) {
        float4 an = ((const float4*)anchors)[a];
        const float ax1 = an.x, ay1 = an.y, ax2 = an.z, ay2 = an.w;
        const float sa = (ax2 - ax1) * (ay2 - ay1);

        float m4 = -1e30f, m5 = -1e30f;
        #pragma unroll 5
        for (int j = 0; j < nv; ++j) {
            float4 bx = sbox[j];
            float4 au = saux[j];
            float iw = fmaxf(fminf(ax2, bx.z) - fmaxf(ax1, bx.x), 0.0f);
            float ih = fminf(ay2, bx.w) - fmaxf(ay1, bx.y);
            m4 = fmaxf(m4, __fmaf_rn(iw, ih, -au.x));
            m5 = fmaxf(m5, __fmaf_rn(iw, ih, -au.y));
        }
        const bool pos = (m5 >= sa * (1.0f / 3.0f));
        const bool neg = (m4 <  sa * (2.0f / 7.0f));
        g_wgt[b * AA + a] = (pos || neg) ? 1.0f : 0.0f;
        if (pos) splist[atomicAdd(&spcnt, 1)] = tid;
    }
    __syncthreads();
    const int nposblk = spcnt;

    // ---- compacted positives ----
    if (tid < nposblk) {
        const int at = splist[tid];
        const int ag = blockIdx.x * TPB + at;
        float4 an = ((const float4*)anchors)[ag];
        const float ax1 = an.x, ay1 = an.y, ax2 = an.z, ay2 = an.w;
        const float aw = ax2 - ax1, ah = ay2 - ay1;
        const float sa = aw * ah;

        float bi = -1.0f, bu = 1.0f;
        int bj = 0;
        for (int j = 0; j < nv; ++j) {
            float4 bx = sbox[j];
            float iw = fmaxf(fminf(ax2, bx.z) - fmaxf(ax1, bx.x), 0.0f);
            float ih = fmaxf(fminf(ay2, bx.w) - fmaxf(ay1, bx.y), 0.0f);
            float inter = iw * ih;
            float ua = fmaxf(sa + saux[j].z - inter, 1e-8f);
            if (inter * bu > bi * ua) { bi = inter; bu = ua; bj = j; }
        }

        int c = __float_as_int(saux[bj].w) - 1;
        float praw = __ldg(logits + ((size_t)b * AA + ag) * KK + c);
        float p = fminf(fmaxf(praw, 1e-4f), 1.0f - 1e-4f);
        float q = 1.0f - p;
        s = (1.0f / 3.0f) * q * q * __log2f(p) - p * p * __log2f(q);

        float4 gb = sbox[bj];
        float acx = ax1 + 0.5f * aw;
        float acy = ay1 + 0.5f * ah;
        float gw0 = gb.z - gb.x, gh0 = gb.w - gb.y;
        float gcx = gb.x + 0.5f * gw0;
        float gcy = gb.y + 0.5f * gh0;
        float gw = fmaxf(gw0, 1.0f), gh = fmaxf(gh0, 1.0f);
        float4 rp = ((const float4*)regp)[b * AA + ag];
        float t0 = ((gcx - acx) / aw) * 10.0f;
        float t1 = ((gcy - acy) / ah) * 10.0f;
        float t2 = logf(gw / aw) * 5.0f;
        float t3 = logf(gh / ah) * 5.0f;
        rsum = smooth_l1(t0 - rp.x) + smooth_l1(t1 - rp.y)
             + smooth_l1(t2 - rp.z) + smooth_l1(t3 - rp.w);
    }

    #pragma unroll
    for (int o = 16; o > 0; o >>= 1) {
        s    += __shfl_down_sync(0xffffffffu, s, o);
        rsum += __shfl_down_sync(0xffffffffu, rsum, o);
    }
    int lane = tid & 31, wid = tid >> 5;
    if (lane == 0) { wsum[wid] = s; wsum2[wid] = rsum; }
    __syncthreads();
    if (tid == 0) {
        float t = 0.0f, t2 = 0.0f;
        #pragma unroll
        for (int i = 0; i < 8; ++i) { t += wsum[i]; t2 += wsum2[i]; }
        if (t != 0.0f)  atomicAdd(&g_cls_raw[b], t);
        if (t2 != 0.0f) atomicAdd(&g_reg_raw[b], t2);
        if (nposblk)    atomicAdd(&g_numpos[b], nposblk);
    }
}

// ============================================================================
// Kernel 2: pure-stream weighted focal sweep + finalize
// ============================================================================
__global__ __launch_bounds__(TPB, 8) void sweep_kernel(
    const float* __restrict__ logits,
    float* __restrict__ out)
{
    const int b = blockIdx.y;
    const float4* __restrict__ L4 = (const float4*)(logits + (size_t)b * AA * KK);
    const float*  __restrict__ W  = g_wgt + b * AA;
    const unsigned N4 = AA * (KK / 4);                  // 982080
    const unsigned stride = NBLKX_SWP * TPB;            // 37888
    unsigned i = blockIdx.x * TPB + threadIdx.x;

    float s0 = 0.0f, s1 = 0.0f, s2 = 0.0f, s3 = 0.0f;
    for (; i + 3 * stride < N4; i += 4 * stride) {
        // 4 independent load chains (logits + weights) -> high MLP
        float4 p0 = L4[i];
        float4 p1 = L4[i + stride];
        float4 p2 = L4[i + 2 * stride];
        float4 p3 = L4[i + 3 * stride];
        float w0 = __ldg(W + i / 20u);
        float w1 = __ldg(W + (i + stride) / 20u);
        float w2 = __ldg(W + (i + 2 * stride) / 20u);
        float w3 = __ldg(W + (i + 3 * stride) / 20u);
        s0 += w0 * focal4(p0);
        s1 += w1 * focal4(p1);
        s2 += w2 * focal4(p2);
        s3 += w3 * focal4(p3);
    }
    for (; i < N4; i += stride)
        s0 += __ldg(W + i / 20u) * focal4(L4[i]);
    float s = (s0 + s1) + (s2 + s3);

    // block reduction -> one atomic
    __shared__ float wsum[8];
    #pragma unroll
    for (int o = 16; o > 0; o >>= 1)
        s += __shfl_down_sync(0xffffffffu, s, o);
    int lane = threadIdx.x & 31, wid = threadIdx.x >> 5;
    if (lane == 0) wsum[wid] = s;
    __syncthreads();

    if (threadIdx.x == 0) {
        float t = 0.0f;
        #pragma unroll
        for (int k = 0; k < 8; ++k) t += wsum[k];
        atomicAdd(&g_cls_raw[b], t);

        __threadfence();
        unsigned int prev = atomicAdd(&g_done, 1u);
        if (prev == NBLKS_SWP - 1) {
            float cm = 0.0f, rm = 0.0f;
            #pragma unroll
            for (int bb = 0; bb < BB; ++bb) {
                float np = fmaxf((float)g_numpos[bb], 1.0f);
                cm += (-0.75f * 0.69314718055994531f) * g_cls_raw[bb] / np;
                rm += g_reg_raw[bb] / (4.0f * np);
                g_cls_raw[bb] = 0.0f;
                g_reg_raw[bb] = 0.0f;
                g_numpos[bb] = 0;
            }
            cm *= (1.0f / (float)BB);
            rm *= (1.0f / (float)BB);
            out[0] = cm;
            out[1] = rm;
            out[2] = cm + rm;
            g_done = 0u;
        }
    }
}

extern "C" void kernel_launch(void* const* d_in, const int* in_sizes, int n_in,
                              void* d_out, int out_size) {
    const float* logits  = (const float*)d_in[0];
    const float* regp    = (const float*)d_in[1];
    const float* anchors = (const float*)d_in[2];
    const float* boxes   = (const float*)d_in[3];
    const int*   cls     = (const int*)d_in[4];
    float* out = (float*)d_out;

    dim3 gscr(NBLKX_SCR, BB);
    screen_kernel<<<gscr, TPB>>>(logits, regp, anchors, boxes, cls);
    dim3 gswp(NBLKX_SWP, BB);
    sweep_kernel<<<gswp, TPB>>>(logits, out);
}

// round 12
// speedup vs baseline: 1.2536x; 1.2536x over previous
#include <cuda_runtime.h>
#include <math.h>

#define BB 8
#define AA 49104
#define MM 50
#define KK 80
#define TPB 256
#define ANCH_PER_BLK 256
#define NBLKX ((AA + ANCH_PER_BLK - 1) / ANCH_PER_BLK)   // 192
#define NBLKS (NBLKX * BB)                               // 1536

// zero-initialized at module load; finalizer re-zeros after each consume,
// so every graph replay starts clean.
__device__ float g_cls_raw[BB];
__device__ float g_reg_raw[BB];
__device__ int   g_numpos[BB];
__device__ unsigned int g_done;

__device__ __forceinline__ float smooth_l1(float d) {
    const float BETA = 1.0f / 9.0f;
    float ad = fabsf(d);
    return (ad <= BETA) ? (4.5f * ad * ad) : (ad - 0.5f * BETA);
}

// focal bulk term for one float4 of probabilities: sum p^2 * log2(1-p)
__device__ __forceinline__ float focal4(float4 p4) {
    return p4.x * p4.x * __log2f(1.0f - p4.x)
         + p4.y * p4.y * __log2f(1.0f - p4.y)
         + p4.z * p4.z * __log2f(1.0f - p4.z)
         + p4.w * p4.w * __log2f(1.0f - p4.w);
}

__global__ __launch_bounds__(TPB, 6) void retina_fused_kernel(
    const float* __restrict__ logits,   // (B,A,K)
    const float* __restrict__ regp,     // (B,A,4)
    const float* __restrict__ anchors,  // (A,4)
    const float* __restrict__ boxes,    // (B,M,4)
    const int*   __restrict__ cls,      // (B,M)
    float* __restrict__ out)
{
    const int b = blockIdx.y;
    const int tid = threadIdx.x;
    const int lane = tid & 31;
    const int wrp = tid >> 5;
    const int aStart = blockIdx.x * ANCH_PER_BLK;

    __shared__ float4 sbox[MM];            // box coords
    __shared__ float4 saux[MM];            // (2/7)sb, (1/3)sb, sb, cls-bits
    __shared__ float  swgt[ANCH_PER_BLK];  // per-anchor weight (warp-local use)
    __shared__ int    spcnt, snv;
    __shared__ float  wsum[8], wsum2[8];

    if (tid == 0) { spcnt = 0; snv = MM; }
    __syncthreads();
    if (tid < MM) {
        float4 bx = ((const float4*)boxes)[b * MM + tid];
        float sb = (bx.z - bx.x) * (bx.w - bx.y);
        sbox[tid] = bx;
        float4 au;
        au.x = sb * (2.0f / 7.0f);   // 0.4/(1+0.4) * sb
        au.y = sb * (1.0f / 3.0f);   // 0.5/(1+0.5) * sb
        au.z = sb;
        au.w = __int_as_float(cls[b * MM + tid]);
        saux[tid] = au;
        if (bx.x == -1.0f) atomicMin(&snv, tid);   // valid-first padding
    }
    __syncthreads();
    const int nv = snv;   // uniform -> no divergence

    float s = 0.0f;      // classification partial (units of p^2*log2(...))
    float rsum = 0.0f;   // regression partial

    // ======== warp-private pipeline: each warp screens + streams its own
    // ======== 32-anchor span; no block barrier between phases ========
    const int aw0 = aStart + (wrp << 5);   // warp's first anchor
    const int myA = aw0 + lane;

    // ---- screen own anchor (iou >= t <=> inter >= t/(1+t)*(sa+sb)) ----
    bool pos = false;
    {
        float myw = 0.0f;
        if (myA < AA) {
            float4 an = ((const float4*)anchors)[myA];
            const float ax1 = an.x, ay1 = an.y, ax2 = an.z, ay2 = an.w;
            const float aw = ax2 - ax1, ah = ay2 - ay1;
            const float sa = aw * ah;

            float m4 = -1e30f, m5 = -1e30f;
            #pragma unroll 5
            for (int j = 0; j < nv; ++j) {
                float4 bx = sbox[j];
                float4 au = saux[j];
                float iw = fmaxf(fminf(ax2, bx.z) - fmaxf(ax1, bx.x), 0.0f);
                float ih = fminf(ay2, bx.w) - fmaxf(ay1, bx.y);
                m4 = fmaxf(m4, __fmaf_rn(iw, ih, -au.x));
                m5 = fmaxf(m5, __fmaf_rn(iw, ih, -au.y));
            }
            pos = (m5 >= sa * (1.0f / 3.0f));              // iou_max >= 0.5
            const bool neg = (m4 <  sa * (2.0f / 7.0f));   // iou_max < 0.4
            myw = (pos || neg) ? 1.0f : 0.0f;

            // ---- rare positives: predicated in-warp (no compaction) ----
            if (pos) {
                float bi = -1.0f, bu = 1.0f;
                int bj = 0;
                for (int j = 0; j < nv; ++j) {
                    float4 bx = sbox[j];
                    float iw = fmaxf(fminf(ax2, bx.z) - fmaxf(ax1, bx.x), 0.0f);
                    float ih = fmaxf(fminf(ay2, bx.w) - fmaxf(ay1, bx.y), 0.0f);
                    float inter = iw * ih;
                    float ua = fmaxf(sa + saux[j].z - inter, 1e-8f);
                    if (inter * bu > bi * ua) { bi = inter; bu = ua; bj = j; }
                }
                int c = __float_as_int(saux[bj].w) - 1;
                float praw = __ldg(logits + ((size_t)b * AA + myA) * KK + c);
                float p = fminf(fmaxf(praw, 1e-4f), 1.0f - 1e-4f);
                float q = 1.0f - p;
                s += (1.0f / 3.0f) * q * q * __log2f(p) - p * p * __log2f(q);

                float4 gb = sbox[bj];
                float acx = ax1 + 0.5f * aw;
                float acy = ay1 + 0.5f * ah;
                float gw0 = gb.z - gb.x, gh0 = gb.w - gb.y;
                float gcx = gb.x + 0.5f * gw0;
                float gcy = gb.y + 0.5f * gh0;
                float gw = fmaxf(gw0, 1.0f), gh = fmaxf(gh0, 1.0f);
                float4 rp = ((const float4*)regp)[b * AA + myA];
                float t0 = ((gcx - acx) / aw) * 10.0f;
                float t1 = ((gcy - acy) / ah) * 10.0f;
                float t2 = logf(gw / aw) * 5.0f;
                float t3 = logf(gh / ah) * 5.0f;
                rsum = smooth_l1(t0 - rp.x) + smooth_l1(t1 - rp.y)
                     + smooth_l1(t2 - rp.z) + smooth_l1(t3 - rp.w);
            }
        }
        swgt[tid] = myw;
        unsigned int bal = __ballot_sync(0xffffffffu, pos);
        if (lane == 0 && bal) atomicAdd(&g_numpos[b], __popc(bal));
        __syncwarp();   // warp-local: swgt[warp span] visible
    }

    // ---- stream own 32-anchor sub-tile (10 KB contiguous per warp) ----
    {
        const int nA = min(32, AA - aw0);
        if (nA > 0) {
            const float4* wt4 = (const float4*)(logits + ((size_t)b * AA + aw0) * KK);
            const int wbase = wrp << 5;
            if (nA == 32) {
                // full warp tile: 640 float4s, 20 coalesced iterations
                #pragma unroll 5
                for (int k = 0; k < 32 * (KK / 4) / 32; ++k) {
                    int j = lane + (k << 5);
                    float w = swgt[wbase + j / (KK / 4)];
                    s += w * focal4(wt4[j]);
                }
            } else {
                const int n4 = nA * (KK / 4);
                for (int j = lane; j < n4; j += 32) {
                    float w = swgt[wbase + j / (KK / 4)];
                    s += w * focal4(wt4[j]);
                }
            }
        }
    }

    // ---- block reduction, one atomic each ----
    #pragma unroll
    for (int o = 16; o > 0; o >>= 1) {
        s    += __shfl_down_sync(0xffffffffu, s, o);
        rsum += __shfl_down_sync(0xffffffffu, rsum, o);
    }
    if (lane == 0) { wsum[wrp] = s; wsum2[wrp] = rsum; }
    __syncthreads();

    if (tid == 0) {
        float t = 0.0f, t2 = 0.0f;
        #pragma unroll
        for (int i = 0; i < 8; ++i) { t += wsum[i]; t2 += wsum2[i]; }
        if (t != 0.0f)  atomicAdd(&g_cls_raw[b], t);
        if (t2 != 0.0f) atomicAdd(&g_reg_raw[b], t2);

        // ---- last block finalizes + resets ----
        __threadfence();
        unsigned int prev = atomicAdd(&g_done, 1u);
        if (prev == NBLKS - 1) {
            float cm = 0.0f, rm = 0.0f;
            #pragma unroll
            for (int bb = 0; bb < BB; ++bb) {
                float np = fmaxf((float)g_numpos[bb], 1.0f);
                cm += (-0.75f * 0.69314718055994531f) * g_cls_raw[bb] / np;
                rm += g_reg_raw[bb] / (4.0f * np);
                g_cls_raw[bb] = 0.0f;
                g_reg_raw[bb] = 0.0f;
                g_numpos[bb] = 0;
            }
            cm *= (1.0f / (float)BB);
            rm *= (1.0f / (float)BB);
            out[0] = cm;
            out[1] = rm;
            out[2] = cm + rm;
            g_done = 0u;
        }
    }
}

extern "C" void kernel_launch(void* const* d_in, const int* in_sizes, int n_in,
                              void* d_out, int out_size) {
    const float* logits  = (const float*)d_in[0];
    const float* regp    = (const float*)d_in[1];
    const float* anchors = (const float*)d_in[2];
    const float* boxes   = (const float*)d_in[3];
    const int*   cls     = (const int*)d_in[4];
    float* out = (float*)d_out;

    dim3 grid(NBLKX, BB);
    retina_fused_kernel<<<grid, TPB>>>(logits, regp, anchors, boxes, cls, out);
}